// round 2
// baseline (speedup 1.0000x reference)
#include <cuda_runtime.h>
#include <cuda_bf16.h>
#include <cstdint>

#define N_NODES 100000
#define N_EDGES 800000
#define F 128
#define C 64

// Scratch (static device globals — no runtime allocation allowed)
__device__ float g_y[(size_t)N_NODES * C];      // y = x @ W^T
__device__ float g_accum[(size_t)N_NODES * C];  // y[v] + sum_{u->v} y[u]
__device__ float g_deg[N_NODES];                // 1 + in_degree
__device__ int   g_is64;                        // edge index dtype flag

// ---------------------------------------------------------------------------
// Probe: are edge indices int64 or int32? Values are < 100000, so if int64,
// every odd 32-bit word of the first 256 entries is zero. If int32, the odds
// are random node ids (P(all 256 zero) ~ 0).
// ---------------------------------------------------------------------------
__global__ void detect_kernel(const unsigned int* __restrict__ p) {
    if (threadIdx.x == 0 && blockIdx.x == 0) {
        int all0 = 1;
        for (int i = 0; i < 256; i++) {
            if (p[2 * i + 1] != 0u) { all0 = 0; break; }
        }
        g_is64 = all0;
    }
}

// ---------------------------------------------------------------------------
// Kernel 1: y = x @ W^T. W (64x128 fp32 = 32KB) staged in smem.
// One thread per node, 64 accumulators, float4 loads everywhere.
// Also seeds accum = y (self term) and deg = 1 (the +1).
// ---------------------------------------------------------------------------
__global__ void __launch_bounds__(128) gemm_kernel(const float* __restrict__ x,
                                                   const float* __restrict__ W) {
    __shared__ float Ws[C * F];
    const int tid = threadIdx.x;

    const float4* W4  = reinterpret_cast<const float4*>(W);
    float4*       Ws4 = reinterpret_cast<float4*>(Ws);
    for (int i = tid; i < (C * F) / 4; i += blockDim.x) Ws4[i] = W4[i];
    __syncthreads();

    const int node = blockIdx.x * blockDim.x + tid;
    if (node >= N_NODES) return;

    float acc[C];
#pragma unroll
    for (int c = 0; c < C; c++) acc[c] = 0.0f;

    const float4* x4 = reinterpret_cast<const float4*>(x + (size_t)node * F);

#pragma unroll 1
    for (int k = 0; k < F / 4; k++) {
        float4 xv = x4[k];
#pragma unroll
        for (int c = 0; c < C; c++) {
            float4 wv = Ws4[c * (F / 4) + k];
            acc[c] += xv.x * wv.x;
            acc[c] += xv.y * wv.y;
            acc[c] += xv.z * wv.z;
            acc[c] += xv.w * wv.w;
        }
    }

    float4* y4 = reinterpret_cast<float4*>(g_y     + (size_t)node * C);
    float4* a4 = reinterpret_cast<float4*>(g_accum + (size_t)node * C);
#pragma unroll
    for (int c4 = 0; c4 < C / 4; c4++) {
        float4 v = make_float4(acc[4 * c4], acc[4 * c4 + 1],
                               acc[4 * c4 + 2], acc[4 * c4 + 3]);
        y4[c4] = v;
        a4[c4] = v;
    }
    g_deg[node] = 1.0f;
}

// ---------------------------------------------------------------------------
// Kernel 2: edge scatter. 16 lanes per edge; each lane gathers one float4 of
// y[src] (L2-resident) and issues a vector reduction into accum[dst].
// ---------------------------------------------------------------------------
__global__ void __launch_bounds__(256) edge_kernel(const void* __restrict__ src_p,
                                                   const void* __restrict__ dst_p) {
    const int e    = blockIdx.x * (blockDim.x / 16) + (threadIdx.x >> 4);
    const int lane = threadIdx.x & 15;
    if (e >= N_EDGES) return;

    const int is64 = g_is64;  // uniform load, resolves once per warp
    long long s, d;
    if (is64) {
        s = reinterpret_cast<const long long*>(src_p)[e];
        d = reinterpret_cast<const long long*>(dst_p)[e];
    } else {
        s = reinterpret_cast<const int*>(src_p)[e];
        d = reinterpret_cast<const int*>(dst_p)[e];
    }

    const float4* ys = reinterpret_cast<const float4*>(g_y + (size_t)s * C);
    float4 v = ys[lane];

    float* ap = g_accum + (size_t)d * C + lane * 4;
    asm volatile("red.global.add.v4.f32 [%0], {%1, %2, %3, %4};"
                 :: "l"(ap), "f"(v.x), "f"(v.y), "f"(v.z), "f"(v.w)
                 : "memory");

    if (lane == 0) atomicAdd(g_deg + d, 1.0f);
}

// ---------------------------------------------------------------------------
// Kernel 3: out = accum / deg + b. Streaming, float4 per thread.
// ---------------------------------------------------------------------------
__global__ void __launch_bounds__(256) final_kernel(const float* __restrict__ b,
                                                    float* __restrict__ out) {
    const int i = blockIdx.x * blockDim.x + threadIdx.x;  // float4 index
    if (i >= (N_NODES * C) / 4) return;

    const int node = i / (C / 4);
    const int c4   = i % (C / 4);

    float4 a    = reinterpret_cast<const float4*>(g_accum)[i];
    float  dinv = 1.0f / g_deg[node];
    float4 bv   = reinterpret_cast<const float4*>(b)[c4];

    float4 o;
    o.x = a.x * dinv + bv.x;
    o.y = a.y * dinv + bv.y;
    o.z = a.z * dinv + bv.z;
    o.w = a.w * dinv + bv.w;
    reinterpret_cast<float4*>(out)[i] = o;
}

// ---------------------------------------------------------------------------
// Launcher. Inputs (metadata order): x, edge_src, edge_dst, W_neigh, b_neigh.
// ---------------------------------------------------------------------------
extern "C" void kernel_launch(void* const* d_in, const int* in_sizes, int n_in,
                              void* d_out, int out_size) {
    const float* x   = (const float*)d_in[0];
    const void*  es  = d_in[1];
    const void*  ed  = d_in[2];
    const float* W   = (const float*)d_in[3];
    const float* b   = (const float*)d_in[4];
    float*       out = (float*)d_out;

    detect_kernel<<<1, 32>>>((const unsigned int*)es);

    {
        const int threads = 128;
        const int blocks  = (N_NODES + threads - 1) / threads;
        gemm_kernel<<<blocks, threads>>>(x, W);
    }
    {
        const int threads = 256;
        const int edges_per_block = threads / 16;
        const int blocks = (N_EDGES + edges_per_block - 1) / edges_per_block;
        edge_kernel<<<blocks, threads>>>(es, ed);
    }
    {
        const int total4  = (N_NODES * C) / 4;
        const int threads = 256;
        const int blocks  = (total4 + threads - 1) / threads;
        final_kernel<<<blocks, threads>>>(b, out);
    }
}